// round 7
// baseline (speedup 1.0000x reference)
#include <cuda_runtime.h>
#include <cuda_bf16.h>
#include <math.h>
#include <stdint.h>

// BiRNN (2-layer bidirectional LSTM), B=32, T=512, H=1024.
// Round 7: recurrent kernel: 512 threads (16 warps), K-tile=128 (8 phases),
// resident Whh_hi in smem, cp.async G-prefetch into gates buffer.

#define Bsz 32
#define Tsz 512
#define Hsz 1024
#define G4  4096
#define MROWS (Tsz * Bsz) // 16384

// big input GEMM tiling (unchanged)
#define MT 128
#define NT 128
#define KT 32
#define KP 40
#define BUFB (MT * KP * 2)
#define STAGEB (4 * BUFB)
#define SMEM_GEMM (2 * STAGEB)   // 81920

// recurrent tiling: K-tile 128, pitch 272B (136 bf16) -> conflict-free ldmatrix
#define RPB 272                          // row pitch bytes
#define R_TILE_A (32 * RPB)              // 8704
#define R_TILE_B (64 * RPB)              // 17408
#define R_BH_TOT (8 * R_TILE_B)          // resident Whh_hi: 139264
#define R_STGSZ (2 * R_TILE_A + R_TILE_B)// stage: A_hi, A_lo, B_lo = 34816
#define OFF_STG R_BH_TOT
#define OFF_GATES (R_BH_TOT + 2 * R_STGSZ) // 208896
#define GATE_P 68
#define OFF_C (OFF_GATES + 32 * GATE_P * 4) // 217600
#define SMEM_R3 (OFF_C + 32 * 16 * 4)       // 219648

// ---------------- device globals -------------------------------------------
__device__ float g_G[2][(size_t)MROWS * G4];
__device__ __nv_bfloat16 g_Ahi[2][(size_t)MROWS * Hsz];
__device__ __nv_bfloat16 g_Alo[2][(size_t)MROWS * Hsz];
__device__ __nv_bfloat16 g_Whi[2][(size_t)G4 * Hsz];
__device__ __nv_bfloat16 g_Wlo[2][(size_t)G4 * Hsz];
__device__ __nv_bfloat16 g_Rhi[2][(size_t)G4 * Hsz];    // Whh split + block-reordered
__device__ __nv_bfloat16 g_Rlo[2][(size_t)G4 * Hsz];
__device__ __nv_bfloat16 g_hh[2][2][2][Bsz * Hsz];      // [parity][dir][hi/lo][b*H+k]
__device__ unsigned g_cnt[4][64];
__device__ unsigned g_cnt2;
__device__ volatile unsigned g_gen;

// ---------------- helpers ---------------------------------------------------
__device__ __forceinline__ uint32_t smem_u32(const void* p) {
    uint32_t a;
    asm("{ .reg .u64 t; cvta.to.shared.u64 t, %1; cvt.u32.u64 %0, t; }" : "=r"(a) : "l"(p));
    return a;
}
__device__ __forceinline__ void cp16(uint32_t dst, const void* src) {
    asm volatile("cp.async.cg.shared.global [%0], [%1], 16;" :: "r"(dst), "l"(src));
}
#define CP_COMMIT() asm volatile("cp.async.commit_group;" ::: "memory")
#define CP_WAIT(n)  asm volatile("cp.async.wait_group %0;" :: "n"(n) : "memory")

__device__ __forceinline__ void ldm4(uint32_t* r, uint32_t a) {
    asm volatile("ldmatrix.sync.aligned.m8n8.x4.shared.b16 {%0,%1,%2,%3}, [%4];"
        : "=r"(r[0]), "=r"(r[1]), "=r"(r[2]), "=r"(r[3]) : "r"(a));
}
__device__ __forceinline__ void ldm2(uint32_t* r, uint32_t a) {
    asm volatile("ldmatrix.sync.aligned.m8n8.x2.shared.b16 {%0,%1}, [%2];"
        : "=r"(r[0]), "=r"(r[1]) : "r"(a));
}
__device__ __forceinline__ void mma16816(float* d, const uint32_t* a, const uint32_t* b) {
    asm volatile(
        "mma.sync.aligned.m16n8k16.row.col.f32.bf16.bf16.f32 "
        "{%0,%1,%2,%3}, {%4,%5,%6,%7}, {%8,%9}, {%0,%1,%2,%3};"
        : "+f"(d[0]), "+f"(d[1]), "+f"(d[2]), "+f"(d[3])
        : "r"(a[0]), "r"(a[1]), "r"(a[2]), "r"(a[3]), "r"(b[0]), "r"(b[1]));
}

__device__ __forceinline__ void grid_barrier2(int bid) {
    __syncthreads();
    if (threadIdx.x == 0) {
        __threadfence();
        unsigned gen = g_gen;
        unsigned r = atomicAdd(&g_cnt[bid & 3][0], 1u);
        bool released = false;
        if (r == 31) {
            unsigned r2 = atomicAdd(&g_cnt2, 1u);
            if (r2 == 3) {
                g_cnt[0][0] = 0; g_cnt[1][0] = 0; g_cnt[2][0] = 0; g_cnt[3][0] = 0;
                g_cnt2 = 0;
                __threadfence();
                g_gen = gen + 1;
                released = true;
            }
        }
        if (!released) { while (g_gen == gen) { } }
        __threadfence();
    }
    __syncthreads();
}

__device__ __forceinline__ void split_bf16(float v, __nv_bfloat16& hi, __nv_bfloat16& lo) {
    hi = __float2bfloat16(v);
    lo = __float2bfloat16(v - __bfloat162float(hi));
}
__device__ __forceinline__ float sigf(float v) { return 1.0f / (1.0f + __expf(-v)); }

// ---------------- conversion kernels ---------------------------------------
__global__ void conv_x_kernel(const float* __restrict__ x) {
    const size_t N = (size_t)MROWS * Hsz;
    for (size_t i = blockIdx.x * blockDim.x + threadIdx.x; i < N; i += (size_t)gridDim.x * blockDim.x) {
        int r = (int)(i >> 10), h = (int)(i & 1023);
        int b = r & 31, t = r >> 5;
        float v = x[((size_t)b * Tsz + t) * Hsz + h];
        __nv_bfloat16 hi, lo; split_bf16(v, hi, lo);
        g_Ahi[0][i] = hi; g_Alo[0][i] = lo;
    }
}

__global__ void conv_w_kernel(const float* __restrict__ Wf, const float* __restrict__ Wb, int layer) {
    const size_t N = (size_t)G4 * Hsz;
    for (size_t i = blockIdx.x * blockDim.x + threadIdx.x; i < 2 * N; i += (size_t)gridDim.x * blockDim.x) {
        int d = i >= N;
        size_t j = d ? i - N : i;
        float v = (d ? Wb : Wf)[(size_t)layer * N + j];
        __nv_bfloat16 hi, lo; split_bf16(v, hi, lo);
        g_Whi[d][j] = hi; g_Wlo[d][j] = lo;
    }
}

__global__ void conv_rw_kernel(const float* __restrict__ Wf, const float* __restrict__ Wb, int layer) {
    const size_t N = (size_t)G4 * Hsz;
    for (size_t i = blockIdx.x * blockDim.x + threadIdx.x; i < 2 * N; i += (size_t)gridDim.x * blockDim.x) {
        int d = i >= N;
        size_t j = d ? i - N : i;
        int r = (int)(j >> 10), k = (int)(j & 1023);
        int g = r >> 10, h = r & 1023;
        int xx = h >> 4, hl = h & 15;
        int nr = xx * 64 + g * 16 + hl;
        float v = (d ? Wb : Wf)[(size_t)layer * N + j];
        __nv_bfloat16 hi, lo; split_bf16(v, hi, lo);
        g_Rhi[d][(size_t)nr * Hsz + k] = hi;
        g_Rlo[d][(size_t)nr * Hsz + k] = lo;
    }
}

// ---------------- HMMA big input GEMM (unchanged) --------------------------
__global__ void __launch_bounds__(256, 2) tc_gemm_kernel(
    const float* __restrict__ b_f, const float* __restrict__ b_b, int layer)
{
    extern __shared__ __align__(16) char sm[];
    const int d = blockIdx.z;
    const int mBlk = blockIdx.y * MT;
    const int nBlk = blockIdx.x * NT;
    const int tid = threadIdx.x, wid = tid >> 5, lid = tid & 31;

    const int aSel = (layer == 0) ? 0 : d;
    const __nv_bfloat16* __restrict__ Ah = g_Ahi[aSel] + (size_t)mBlk * Hsz;
    const __nv_bfloat16* __restrict__ Al = g_Alo[aSel] + (size_t)mBlk * Hsz;
    const __nv_bfloat16* __restrict__ Bh = g_Whi[d] + (size_t)nBlk * Hsz;
    const __nv_bfloat16* __restrict__ Bl = g_Wlo[d] + (size_t)nBlk * Hsz;
    const float* __restrict__ bias = (d == 0 ? b_f : b_b) + (size_t)layer * G4;

    const uint32_t smb = smem_u32(sm);

    const int lr0 = tid >> 2, lc0 = (tid & 3) * 8;
    const int lr1 = (tid + 256) >> 2;

    const int wm = wid & 1, wn = wid >> 1;
    const int ar = lid & 15, acg = lid >> 4;
    const int bnr = ((lid & 16) >> 1) | (lid & 7);
    const int bko = lid & 8;

    float acc[4][4][4] = {};

    {
        const uint32_t base = smb;
        uint32_t d0 = base + (uint32_t)(lr0 * KP + lc0) * 2;
        uint32_t d1 = base + (uint32_t)(lr1 * KP + lc0) * 2;
        size_t s0 = (size_t)lr0 * Hsz + lc0;
        size_t s1 = (size_t)lr1 * Hsz + lc0;
        cp16(d0 + 0 * BUFB, Ah + s0); cp16(d1 + 0 * BUFB, Ah + s1);
        cp16(d0 + 1 * BUFB, Al + s0); cp16(d1 + 1 * BUFB, Al + s1);
        cp16(d0 + 2 * BUFB, Bh + s0); cp16(d1 + 2 * BUFB, Bh + s1);
        cp16(d0 + 3 * BUFB, Bl + s0); cp16(d1 + 3 * BUFB, Bl + s1);
        CP_COMMIT();
    }

    const int NSTG = Hsz / KT; // 32
    for (int s = 0; s < NSTG; s++) {
        if (s + 1 < NSTG) {
            const int k0 = (s + 1) * KT;
            const uint32_t base = smb + ((s + 1) & 1) * STAGEB;
            uint32_t d0 = base + (uint32_t)(lr0 * KP + lc0) * 2;
            uint32_t d1 = base + (uint32_t)(lr1 * KP + lc0) * 2;
            size_t s0 = (size_t)lr0 * Hsz + k0 + lc0;
            size_t s1 = (size_t)lr1 * Hsz + k0 + lc0;
            cp16(d0 + 0 * BUFB, Ah + s0); cp16(d1 + 0 * BUFB, Ah + s1);
            cp16(d0 + 1 * BUFB, Al + s0); cp16(d1 + 1 * BUFB, Al + s1);
            cp16(d0 + 2 * BUFB, Bh + s0); cp16(d1 + 2 * BUFB, Bh + s1);
            cp16(d0 + 3 * BUFB, Bl + s0); cp16(d1 + 3 * BUFB, Bl + s1);
            CP_COMMIT();
            CP_WAIT(1);
        } else {
            CP_WAIT(0);
        }
        __syncthreads();

        const uint32_t base = smb + (s & 1) * STAGEB;
#pragma unroll
        for (int kc = 0; kc < 2; kc++) {
            uint32_t ah[4][4], bh[2][4];
#pragma unroll
            for (int mi = 0; mi < 4; mi++) {
                uint32_t ao = base + (uint32_t)((wm * 64 + mi * 16 + ar) * KP + kc * 16 + acg * 8) * 2;
                ldm4(ah[mi], ao);
            }
#pragma unroll
            for (int g = 0; g < 2; g++) {
                uint32_t bo = base + 2 * BUFB
                            + (uint32_t)((wn * 32 + g * 16 + bnr) * KP + kc * 16 + bko) * 2;
                ldm4(bh[g], bo);
            }
#pragma unroll
            for (int mi = 0; mi < 4; mi++)
#pragma unroll
                for (int ni = 0; ni < 4; ni++)
                    mma16816(acc[mi][ni], ah[mi], &bh[ni >> 1][(ni & 1) * 2]);
            {
                uint32_t al[4][4];
#pragma unroll
                for (int mi = 0; mi < 4; mi++) {
                    uint32_t ao = base + BUFB
                                + (uint32_t)((wm * 64 + mi * 16 + ar) * KP + kc * 16 + acg * 8) * 2;
                    ldm4(al[mi], ao);
                }
#pragma unroll
                for (int mi = 0; mi < 4; mi++)
#pragma unroll
                    for (int ni = 0; ni < 4; ni++)
                        mma16816(acc[mi][ni], al[mi], &bh[ni >> 1][(ni & 1) * 2]);
            }
            {
                uint32_t bl[2][4];
#pragma unroll
                for (int g = 0; g < 2; g++) {
                    uint32_t bo = base + 3 * BUFB
                                + (uint32_t)((wn * 32 + g * 16 + bnr) * KP + kc * 16 + bko) * 2;
                    ldm4(bl[g], bo);
                }
#pragma unroll
                for (int mi = 0; mi < 4; mi++)
#pragma unroll
                    for (int ni = 0; ni < 4; ni++)
                        mma16816(acc[mi][ni], ah[mi], &bl[ni >> 1][(ni & 1) * 2]);
            }
        }
        __syncthreads();
    }

    const int er = lid >> 2, ec = (lid & 3) * 2;
#pragma unroll
    for (int mi = 0; mi < 4; mi++) {
#pragma unroll
        for (int ni = 0; ni < 4; ni++) {
            int gm = mBlk + wm * 64 + mi * 16 + er;
            int gn = nBlk + wn * 32 + ni * 8 + ec;
            float bv0 = bias[gn], bv1 = bias[gn + 1];
            float* p0 = g_G[d] + (size_t)gm * G4 + gn;
            p0[0] = acc[mi][ni][0] + bv0;
            p0[1] = acc[mi][ni][1] + bv1;
            float* p1 = p0 + (size_t)8 * G4;
            p1[0] = acc[mi][ni][2] + bv0;
            p1[1] = acc[mi][ni][3] + bv1;
        }
    }
}

// ---------------- persistent HMMA recurrent LSTM ---------------------------
// Grid (64, 2) = 128 blocks, 512 threads (16 warps: wm=wid&1, wn=wid>>1).
// Whh_hi resident in smem; {h_hi, h_lo, Whh_lo} double-buffered K-tile=128;
// g_G prefetched into gates smem via cp.async at step start.
__global__ void __launch_bounds__(512) lstm_hmma_kernel(
    int layer, float* __restrict__ outp, int extra)
{
    extern __shared__ __align__(16) char rsm[];
    const int x = blockIdx.x, d = blockIdx.y;
    const int bid = blockIdx.x + blockIdx.y * 64;
    const int tid = threadIdx.x, wid = tid >> 5, lid = tid & 31;
    const int wm = wid & 1, wn = wid >> 1;   // 2 x 8 warps

    const uint32_t smb = smem_u32(rsm);
    float* gates_s = (float*)(rsm + OFF_GATES);
    float* c_s = (float*)(rsm + OFF_C);

    const __nv_bfloat16* __restrict__ Bh = g_Rhi[d] + (size_t)(x * 64) * Hsz;
    const __nv_bfloat16* __restrict__ Bl = g_Rlo[d] + (size_t)(x * 64) * Hsz;

    const int lrow = tid >> 4, lch = tid & 15;  // row 0..31, 16B chunk 0..15
    const uint32_t doffA = (uint32_t)(lrow * RPB + lch * 16);

    // Preload resident Whh_hi (8 k-tiles of 64x128).
#pragma unroll
    for (int kt = 0; kt < 8; kt++) {
        uint32_t dst = smb + kt * R_TILE_B + doffA;
        const __nv_bfloat16* src = Bh + (size_t)lrow * Hsz + kt * 128 + lch * 8;
        cp16(dst, src);
        cp16(dst + 32 * RPB, src + (size_t)32 * Hsz);
    }
    CP_COMMIT();

    // zero h (both parities, hi & lo) slice + c
    {
        int b = tid >> 4, col = x * 16 + (tid & 15);
        int idx = b * Hsz + col;
        __nv_bfloat16 z = __float2bfloat16(0.f);
        g_hh[0][d][0][idx] = z; g_hh[0][d][1][idx] = z;
        g_hh[1][d][0][idx] = z; g_hh[1][d][1][idx] = z;
        c_s[tid] = 0.f;
    }
    CP_WAIT(0);
    grid_barrier2(bid);

    const int ar = lid & 15, acg = lid >> 4;
    const int bn = lid & 7, bk = lid & 8;

    // G prefetch mapping: seg = tid>>2 -> (b, gate), chunk = tid&3 (4 floats)
    const int gseg_b = tid >> 4;          // (tid>>2)>>2
    const int gseg_g = (tid >> 2) & 3;
    const int gch = tid & 3;
    const uint32_t gdst = smb + OFF_GATES
        + (uint32_t)(gseg_b * GATE_P + gseg_g * 16 + gch * 4) * 4;

    for (int s = 0; s < Tsz; s++) {
        const int p = s & 1;
        const int t = (d == 0) ? s : (Tsz - 1 - s);
        const __nv_bfloat16* __restrict__ Ah = g_hh[p][d][0];
        const __nv_bfloat16* __restrict__ Al = g_hh[p][d][1];

        float accA[4] = {};   // hi x hi
        float accB[4] = {};   // lo x hi + hi x lo

        // prologue: G prefetch + k-tile 0 (stage 0), one group
        cp16(gdst, g_G[d] + (size_t)(t * 32 + gseg_b) * G4 + gseg_g * 1024 + x * 16 + gch * 4);
        {
            const uint32_t base = smb + OFF_STG;
            const size_t soff = (size_t)lrow * Hsz + lch * 8;
            cp16(base + doffA, Ah + soff);
            cp16(base + R_TILE_A + doffA, Al + soff);
            cp16(base + 2 * R_TILE_A + doffA, Bl + soff);
            cp16(base + 2 * R_TILE_A + doffA + 32 * RPB, Bl + soff + (size_t)32 * Hsz);
            CP_COMMIT();
        }

#pragma unroll 1
        for (int kt = 0; kt < 8; kt++) {
            CP_WAIT(0);
            __syncthreads();
            if (kt < 7) {
                const uint32_t base = smb + OFF_STG + ((kt + 1) & 1) * R_STGSZ;
                const size_t soff = (size_t)lrow * Hsz + (kt + 1) * 128 + lch * 8;
                cp16(base + doffA, Ah + soff);
                cp16(base + R_TILE_A + doffA, Al + soff);
                cp16(base + 2 * R_TILE_A + doffA, Bl + soff);
                cp16(base + 2 * R_TILE_A + doffA + 32 * RPB, Bl + soff + (size_t)32 * Hsz);
                CP_COMMIT();
            }

            const uint32_t stg = smb + OFF_STG + (kt & 1) * R_STGSZ;
            const uint32_t bres = smb + kt * R_TILE_B;
#pragma unroll
            for (int kc = 0; kc < 8; kc++) {
                uint32_t ah[4], al[4], bh[2], bl[2];
                uint32_t ao = stg + (uint32_t)((wm * 16 + ar) * RPB) + (uint32_t)(kc * 16 + acg * 8) * 2;
                ldm4(ah, ao);
                ldm4(al, ao + R_TILE_A);
                uint32_t bo = (uint32_t)((wn * 8 + bn) * RPB) + (uint32_t)(kc * 16 + bk) * 2;
                ldm2(bh, bres + bo);
                ldm2(bl, stg + 2 * R_TILE_A + bo);
                mma16816(accA, ah, bh);
                mma16816(accB, al, bh);
                mma16816(accB, ah, bl);
            }
        }
        __syncthreads();

        // epilogue: gates_s (holds prefetched G) += acc
        {
            const int er = lid >> 2, ec = (lid & 3) * 2;
#pragma unroll
            for (int half = 0; half < 2; half++) {
                int b = wm * 16 + er + half * 8;
                float* gp = &gates_s[b * GATE_P + wn * 8 + ec];
                float2 gv = *(float2*)gp;
                gv.x += accA[half * 2 + 0] + accB[half * 2 + 0];
                gv.y += accA[half * 2 + 1] + accB[half * 2 + 1];
                *(float2*)gp = gv;
            }
        }
        __syncthreads();

        // cell update: one (b, hl) per thread
        {
            const int b = tid >> 4;
            const int hl = tid & 15;
            const int np = p ^ 1;
            float gi = gates_s[b * GATE_P + 0 * 16 + hl];
            float gf = gates_s[b * GATE_P + 1 * 16 + hl];
            float gg = gates_s[b * GATE_P + 2 * 16 + hl];
            float go = gates_s[b * GATE_P + 3 * 16 + hl];
            float iv = sigf(gi), fv = sigf(gf), gv = tanhf(gg), ov = sigf(go);
            float cc = c_s[tid];
            float cn = fv * cc + iv * gv;
            float hn = ov * tanhf(cn);
            c_s[tid] = cn;

            int col = x * 16 + hl;
            __nv_bfloat16 hi, lo; split_bf16(hn, hi, lo);
            g_hh[np][d][0][b * Hsz + col] = hi;
            g_hh[np][d][1][b * Hsz + col] = lo;

            if (layer == 0) {
                size_t off = (size_t)(t * 32 + b) * Hsz + col;
                g_Ahi[d][off] = hi;
                g_Alo[d][off] = lo;
            } else {
                outp[((size_t)b * Tsz + t) * (2 * Hsz) + (size_t)d * Hsz + col] = hn;
                if (extra) {
                    outp[(size_t)Bsz * Tsz * 2 * Hsz + (size_t)d * Bsz * Tsz * Hsz
                         + ((size_t)b * Tsz + t) * Hsz + col] = hn;
                }
            }
        }

        grid_barrier2(bid);
    }
}

extern "C" void kernel_launch(void* const* d_in, const int* in_sizes, int n_in,
                              void* d_out, int out_size) {
    const float* x     = (const float*)d_in[0];
    const float* Wih_f = (const float*)d_in[1];
    const float* Whh_f = (const float*)d_in[2];
    const float* b_f   = (const float*)d_in[3];
    const float* Wih_b = (const float*)d_in[4];
    const float* Whh_b = (const float*)d_in[5];
    const float* b_b   = (const float*)d_in[6];
    float* out = (float*)d_out;

    const long long full = (long long)Bsz * Tsz * 4 * Hsz;
    int extra = ((long long)out_size >= full) ? 1 : 0;

    static int attr_done = 0;
    if (!attr_done) {
        cudaFuncSetAttribute(tc_gemm_kernel,
                             cudaFuncAttributeMaxDynamicSharedMemorySize, SMEM_GEMM);
        cudaFuncSetAttribute(lstm_hmma_kernel,
                             cudaFuncAttributeMaxDynamicSharedMemorySize, SMEM_R3);
        attr_done = 1;
    }

    dim3 gemmGrid(G4 / NT, MROWS / MT, 2);   // (32, 128, 2)
    dim3 stepGrid(64, 2);                    // 128 co-resident blocks

    conv_x_kernel<<<2048, 256>>>(x);
    for (int layer = 0; layer < 2; layer++) {
        conv_w_kernel<<<2048, 256>>>(Wih_f, Wih_b, layer);
        conv_rw_kernel<<<2048, 256>>>(Whh_f, Whh_b, layer);
        tc_gemm_kernel<<<gemmGrid, 256, SMEM_GEMM>>>(b_f, b_b, layer);
        lstm_hmma_kernel<<<stepGrid, 512, SMEM_R3>>>(layer, out, extra);
    }
}

// round 8
// speedup vs baseline: 1.1947x; 1.1947x over previous
#include <cuda_runtime.h>
#include <cuda_fp16.h>
#include <math.h>
#include <stdint.h>

// BiRNN (2-layer bidirectional LSTM), B=32, T=512, H=1024.
// Round 8: fp16 arithmetic (A = x/h single fp16; B = W split hi+lo fp16),
// 2 MMA passes instead of 3. Recurrent uses the proven round-6 pipeline
// (2x4 warps 16x16, resident Whh_hi, 3-stage cp.async, K-tile 128) plus
// G-prefetch into smem.

#define Bsz 32
#define Tsz 512
#define Hsz 1024
#define G4  4096
#define MROWS (Tsz * Bsz) // 16384

// big input GEMM tiling
#define MT 128
#define NT 128
#define KT 32
#define KP 40                     // smem pitch in fp16 (80B)
#define BUFB (MT * KP * 2)        // 10240
#define STAGEB (3 * BUFB)         // A, Bh, Bl
#define SMEM_GEMM (2 * STAGEB)    // 61440

// recurrent tiling: K-tile 128 fp16 (256B) padded to 272B pitch
#define RPB 272
#define R_TILEB (64 * RPB)              // 17408
#define R_SA (32 * RPB)                 // 8704
#define R_RES (8 * R_TILEB)             // resident Whh_hi: 139264
#define R_STG (R_SA + R_TILEB)          // stage: A, B_lo = 26112
#define OFF_STG R_RES
#define OFF_GATES (R_RES + 3 * R_STG)   // 217600
#define GATE_P 68
#define OFF_C (OFF_GATES + 32 * GATE_P * 4) // 226304
#define SMEM_R (OFF_C + 2048)               // 228352 (< 232448 max dyn)

// ---------------- device globals -------------------------------------------
__device__ float g_G[2][(size_t)MROWS * G4];                 // x-part gates + bias
__device__ __align__(256) __half g_A16[2][(size_t)MROWS * Hsz];   // activations fp16
__device__ __align__(256) __half g_Wh16[2][(size_t)G4 * Hsz];     // Wih hi
__device__ __align__(256) __half g_Wl16[2][(size_t)G4 * Hsz];     // Wih lo
__device__ __align__(256) __half g_Rh16[2][(size_t)G4 * Hsz];     // Whh hi (reordered)
__device__ __align__(256) __half g_Rl16[2][(size_t)G4 * Hsz];     // Whh lo (reordered)
__device__ __align__(256) __half g_h16[2][2][Bsz * Hsz];          // [parity][dir]
__device__ unsigned g_cnt[4][64];
__device__ unsigned g_cnt2;
__device__ volatile unsigned g_gen;

// ---------------- helpers ---------------------------------------------------
__device__ __forceinline__ uint32_t smem_u32(const void* p) {
    uint32_t a;
    asm("{ .reg .u64 t; cvta.to.shared.u64 t, %1; cvt.u32.u64 %0, t; }" : "=r"(a) : "l"(p));
    return a;
}
__device__ __forceinline__ void cp16(uint32_t dst, const void* src) {
    asm volatile("cp.async.cg.shared.global [%0], [%1], 16;" :: "r"(dst), "l"(src));
}
#define CP_COMMIT() asm volatile("cp.async.commit_group;" ::: "memory")
#define CP_WAIT(n)  asm volatile("cp.async.wait_group %0;" :: "n"(n) : "memory")

__device__ __forceinline__ void ldm4(uint32_t* r, uint32_t a) {
    asm volatile("ldmatrix.sync.aligned.m8n8.x4.shared.b16 {%0,%1,%2,%3}, [%4];"
        : "=r"(r[0]), "=r"(r[1]), "=r"(r[2]), "=r"(r[3]) : "r"(a));
}
__device__ __forceinline__ void mma16816(float* d, const uint32_t* a, const uint32_t* b) {
    asm volatile(
        "mma.sync.aligned.m16n8k16.row.col.f32.f16.f16.f32 "
        "{%0,%1,%2,%3}, {%4,%5,%6,%7}, {%8,%9}, {%0,%1,%2,%3};"
        : "+f"(d[0]), "+f"(d[1]), "+f"(d[2]), "+f"(d[3])
        : "r"(a[0]), "r"(a[1]), "r"(a[2]), "r"(a[3]), "r"(b[0]), "r"(b[1]));
}

__device__ __forceinline__ void grid_barrier2(int bid) {
    __syncthreads();
    if (threadIdx.x == 0) {
        __threadfence();
        unsigned gen = g_gen;
        unsigned r = atomicAdd(&g_cnt[bid & 3][0], 1u);
        bool released = false;
        if (r == 31) {
            unsigned r2 = atomicAdd(&g_cnt2, 1u);
            if (r2 == 3) {
                g_cnt[0][0] = 0; g_cnt[1][0] = 0; g_cnt[2][0] = 0; g_cnt[3][0] = 0;
                g_cnt2 = 0;
                __threadfence();
                g_gen = gen + 1;
                released = true;
            }
        }
        if (!released) { while (g_gen == gen) { } }
        __threadfence();
    }
    __syncthreads();
}

__device__ __forceinline__ void split_f16(float v, __half& hi, __half& lo) {
    hi = __float2half(v);
    lo = __float2half(v - __half2float(hi));
}
__device__ __forceinline__ float sigf(float v) { return 1.0f / (1.0f + __expf(-v)); }

// ---------------- conversion kernels ---------------------------------------
__global__ void conv_x_kernel(const float* __restrict__ x) {
    const size_t N = (size_t)MROWS * Hsz;
    for (size_t i = blockIdx.x * blockDim.x + threadIdx.x; i < N; i += (size_t)gridDim.x * blockDim.x) {
        int r = (int)(i >> 10), h = (int)(i & 1023);
        int b = r & 31, t = r >> 5;
        g_A16[0][i] = __float2half(x[((size_t)b * Tsz + t) * Hsz + h]);
    }
}

__global__ void conv_w_kernel(const float* __restrict__ Wf, const float* __restrict__ Wb, int layer) {
    const size_t N = (size_t)G4 * Hsz;
    for (size_t i = blockIdx.x * blockDim.x + threadIdx.x; i < 2 * N; i += (size_t)gridDim.x * blockDim.x) {
        int d = i >= N;
        size_t j = d ? i - N : i;
        float v = (d ? Wb : Wf)[(size_t)layer * N + j];
        __half hi, lo; split_f16(v, hi, lo);
        g_Wh16[d][j] = hi; g_Wl16[d][j] = lo;
    }
}

// Whh: split + reorder rows: new row = x*64 + gate*16 + hl (orig gate*1024 + x*16 + hl)
__global__ void conv_rw_kernel(const float* __restrict__ Wf, const float* __restrict__ Wb, int layer) {
    const size_t N = (size_t)G4 * Hsz;
    for (size_t i = blockIdx.x * blockDim.x + threadIdx.x; i < 2 * N; i += (size_t)gridDim.x * blockDim.x) {
        int d = i >= N;
        size_t j = d ? i - N : i;
        int r = (int)(j >> 10), k = (int)(j & 1023);
        int g = r >> 10, h = r & 1023;
        int nr = (h >> 4) * 64 + g * 16 + (h & 15);
        float v = (d ? Wb : Wf)[(size_t)layer * N + j];
        __half hi, lo; split_f16(v, hi, lo);
        g_Rh16[d][(size_t)nr * Hsz + k] = hi;
        g_Rl16[d][(size_t)nr * Hsz + k] = lo;
    }
}

// ---------------- HMMA big input GEMM (fp16, 2 passes) ---------------------
__global__ void __launch_bounds__(256, 2) tc_gemm_kernel(
    const float* __restrict__ b_f, const float* __restrict__ b_b, int layer)
{
    extern __shared__ __align__(16) char sm[];
    const int d = blockIdx.z;
    const int mBlk = blockIdx.y * MT;
    const int nBlk = blockIdx.x * NT;
    const int tid = threadIdx.x, wid = tid >> 5, lid = tid & 31;

    const int aSel = (layer == 0) ? 0 : d;
    const __half* __restrict__ Aa = g_A16[aSel] + (size_t)mBlk * Hsz;
    const __half* __restrict__ Bh = g_Wh16[d] + (size_t)nBlk * Hsz;
    const __half* __restrict__ Bl = g_Wl16[d] + (size_t)nBlk * Hsz;
    const float* __restrict__ bias = (d == 0 ? b_f : b_b) + (size_t)layer * G4;

    const uint32_t smb = smem_u32(sm);

    const int lr0 = tid >> 2, lc0 = (tid & 3) * 8;
    const int lr1 = (tid + 256) >> 2;

    const int wm = wid & 1, wn = wid >> 1;
    const int ar = lid & 15, acg = lid >> 4;
    const int bnr = ((lid & 16) >> 1) | (lid & 7);
    const int bko = lid & 8;

    float acc[4][4][4] = {};

    {
        const uint32_t base = smb;
        uint32_t d0 = base + (uint32_t)(lr0 * KP + lc0) * 2;
        uint32_t d1 = base + (uint32_t)(lr1 * KP + lc0) * 2;
        size_t s0 = (size_t)lr0 * Hsz + lc0;
        size_t s1 = (size_t)lr1 * Hsz + lc0;
        cp16(d0 + 0 * BUFB, Aa + s0); cp16(d1 + 0 * BUFB, Aa + s1);
        cp16(d0 + 1 * BUFB, Bh + s0); cp16(d1 + 1 * BUFB, Bh + s1);
        cp16(d0 + 2 * BUFB, Bl + s0); cp16(d1 + 2 * BUFB, Bl + s1);
        CP_COMMIT();
    }

    const int NSTG = Hsz / KT; // 32
    for (int s = 0; s < NSTG; s++) {
        if (s + 1 < NSTG) {
            const int k0 = (s + 1) * KT;
            const uint32_t base = smb + ((s + 1) & 1) * STAGEB;
            uint32_t d0 = base + (uint32_t)(lr0 * KP + lc0) * 2;
            uint32_t d1 = base + (uint32_t)(lr1 * KP + lc0) * 2;
            size_t s0 = (size_t)lr0 * Hsz + k0 + lc0;
            size_t s1 = (size_t)lr1 * Hsz + k0 + lc0;
            cp16(d0 + 0 * BUFB, Aa + s0); cp16(d1 + 0 * BUFB, Aa + s1);
            cp16(d0 + 1 * BUFB, Bh + s0); cp16(d1 + 1 * BUFB, Bh + s1);
            cp16(d0 + 2 * BUFB, Bl + s0); cp16(d1 + 2 * BUFB, Bl + s1);
            CP_COMMIT();
            CP_WAIT(1);
        } else {
            CP_WAIT(0);
        }
        __syncthreads();

        const uint32_t base = smb + (s & 1) * STAGEB;
#pragma unroll
        for (int kc = 0; kc < 2; kc++) {
            uint32_t ah[4][4], bh[2][4], bl[2][4];
#pragma unroll
            for (int mi = 0; mi < 4; mi++) {
                uint32_t ao = base + (uint32_t)((wm * 64 + mi * 16 + ar) * KP + kc * 16 + acg * 8) * 2;
                ldm4(ah[mi], ao);
            }
#pragma unroll
            for (int g = 0; g < 2; g++) {
                uint32_t bo = (uint32_t)((wn * 32 + g * 16 + bnr) * KP + kc * 16 + bko) * 2;
                ldm4(bh[g], base + BUFB + bo);
                ldm4(bl[g], base + 2 * BUFB + bo);
            }
#pragma unroll
            for (int mi = 0; mi < 4; mi++)
#pragma unroll
                for (int ni = 0; ni < 4; ni++)
                    mma16816(acc[mi][ni], ah[mi], &bh[ni >> 1][(ni & 1) * 2]);
#pragma unroll
            for (int mi = 0; mi < 4; mi++)
#pragma unroll
                for (int ni = 0; ni < 4; ni++)
                    mma16816(acc[mi][ni], ah[mi], &bl[ni >> 1][(ni & 1) * 2]);
        }
        __syncthreads();
    }

    const int er = lid >> 2, ec = (lid & 3) * 2;
#pragma unroll
    for (int mi = 0; mi < 4; mi++) {
#pragma unroll
        for (int ni = 0; ni < 4; ni++) {
            int gm = mBlk + wm * 64 + mi * 16 + er;
            int gn = nBlk + wn * 32 + ni * 8 + ec;
            float bv0 = bias[gn], bv1 = bias[gn + 1];
            float* p0 = g_G[d] + (size_t)gm * G4 + gn;
            p0[0] = acc[mi][ni][0] + bv0;
            p0[1] = acc[mi][ni][1] + bv1;
            float* p1 = p0 + (size_t)8 * G4;
            p1[0] = acc[mi][ni][2] + bv0;
            p1[1] = acc[mi][ni][3] + bv1;
        }
    }
}

// ---------------- persistent HMMA recurrent LSTM (fp16, 2 passes) ----------
// Grid (64, 2), 256 threads, 8 warps 2x4 (warp tile 16x16). Whh_hi resident.
__global__ void __launch_bounds__(256) lstm_hmma_kernel(
    int layer, float* __restrict__ outp, int extra)
{
    extern __shared__ __align__(16) char rsm[];
    const int x = blockIdx.x, d = blockIdx.y;
    const int bid = blockIdx.x + blockIdx.y * 64;
    const int tid = threadIdx.x, wid = tid >> 5, lid = tid & 31;
    const int wm = wid & 1, wn = wid >> 1;

    const uint32_t smb = smem_u32(rsm);
    float* gates_s = (float*)(rsm + OFF_GATES);
    float* c_s = (float*)(rsm + OFF_C);

    const __half* __restrict__ Bh = g_Rh16[d] + (size_t)(x * 64) * Hsz;
    const __half* __restrict__ Bl = g_Rl16[d] + (size_t)(x * 64) * Hsz;

    // load maps
    const int arow = tid >> 3, ac2 = (tid & 7) * 2;   // A: 32 rows x 16 chunks
    const int brow = tid >> 2, bc4 = (tid & 3) * 4;   // B: 64 rows x 16 chunks

    // Resident Whh_hi: 8 tiles of 64x128.
#pragma unroll
    for (int kt = 0; kt < 8; kt++) {
        uint32_t dst = smb + kt * R_TILEB + (uint32_t)(brow * RPB + bc4 * 16);
        const __half* src = Bh + (size_t)brow * Hsz + kt * 128 + bc4 * 8;
#pragma unroll
        for (int j = 0; j < 4; j++) cp16(dst + j * 16, src + j * 8);
    }
    CP_COMMIT();

    for (int i = tid; i < 512; i += 256) {
        int b = i >> 4, col = x * 16 + (i & 15);
        g_h16[0][d][b * Hsz + col] = __float2half(0.f);
        g_h16[1][d][b * Hsz + col] = __float2half(0.f);
        c_s[i] = 0.f;
    }
    CP_WAIT(0);
    grid_barrier2(bid);

    // fragment maps (proven in rounds 5-6)
    const int ar = lid & 15, acg = lid >> 4;
    const int bnr = ((lid & 16) >> 1) | (lid & 7);
    const int bk8 = (lid & 8) >> 3;
    const uint32_t aRowOff = (uint32_t)((wm * 16 + ar) * RPB);
    const uint32_t bRowOff = (uint32_t)((wn * 16 + bnr) * RPB);

    // G prefetch map
    const int gb = tid >> 3, gseg = tid & 7;
    const uint32_t gdst = smb + OFF_GATES + (uint32_t)(gb * GATE_P + gseg * 8) * 4;
    const size_t goff0 = (size_t)(gseg >> 1) * 1024 + x * 16 + (gseg & 1) * 8;

    for (int s = 0; s < Tsz; s++) {
        const int p = s & 1;
        const int t = (d == 0) ? s : (Tsz - 1 - s);
        const __half* __restrict__ Ah = g_h16[p][d];

        float accA[2][4] = {};   // A x B_hi
        float accB[2][4] = {};   // A x B_lo

        // G prefetch (own group)
        {
            const float* gsrc = g_G[d] + (size_t)(t * 32 + gb) * G4 + goff0;
            cp16(gdst, gsrc);
            cp16(gdst + 16, gsrc + 4);
            CP_COMMIT();
        }
        // issue k-tiles 0, 1
#pragma unroll
        for (int kt = 0; kt < 2; kt++) {
            const uint32_t base = smb + OFF_STG + kt * R_STG;
            const __half* asrc = Ah + (size_t)arow * Hsz + kt * 128 + ac2 * 8;
            cp16(base + (uint32_t)(arow * RPB + ac2 * 16), asrc);
            cp16(base + (uint32_t)(arow * RPB + ac2 * 16) + 16, asrc + 8);
            const __half* bsrc = Bl + (size_t)brow * Hsz + kt * 128 + bc4 * 8;
            uint32_t bdst = base + R_SA + (uint32_t)(brow * RPB + bc4 * 16);
#pragma unroll
            for (int j = 0; j < 4; j++) cp16(bdst + j * 16, bsrc + j * 8);
            CP_COMMIT();
        }

#pragma unroll 1
        for (int kt = 0; kt < 8; kt++) {
            if (kt < 7) { CP_WAIT(1); } else { CP_WAIT(0); }
            __syncthreads();
            if (kt < 6) {
                const int kn = kt + 2;
                const uint32_t base = smb + OFF_STG + (kn % 3) * R_STG;
                const __half* asrc = Ah + (size_t)arow * Hsz + kn * 128 + ac2 * 8;
                cp16(base + (uint32_t)(arow * RPB + ac2 * 16), asrc);
                cp16(base + (uint32_t)(arow * RPB + ac2 * 16) + 16, asrc + 8);
                const __half* bsrc = Bl + (size_t)brow * Hsz + kn * 128 + bc4 * 8;
                uint32_t bdst = base + R_SA + (uint32_t)(brow * RPB + bc4 * 16);
#pragma unroll
                for (int j = 0; j < 4; j++) cp16(bdst + j * 16, bsrc + j * 8);
                CP_COMMIT();
            }

            const uint32_t stg = smb + OFF_STG + (kt % 3) * R_STG;
            const uint32_t bres = smb + kt * R_TILEB;
#pragma unroll
            for (int kc = 0; kc < 8; kc++) {
                uint32_t ah[4], bh[4], bl[4];
                ldm4(ah, stg + aRowOff + (uint32_t)((kc * 2 + acg) * 16));
                uint32_t bco = (uint32_t)((kc * 2 + bk8) * 16);
                ldm4(bh, bres + bRowOff + bco);
                ldm4(bl, stg + R_SA + bRowOff + bco);
                mma16816(accA[0], ah, &bh[0]);
                mma16816(accA[1], ah, &bh[2]);
                mma16816(accB[0], ah, &bl[0]);
                mma16816(accB[1], ah, &bl[2]);
            }
        }
        __syncthreads();

        // epilogue: gates_s (holds prefetched G) += acc
        {
            const int er = lid >> 2, ec = (lid & 3) * 2;
            const int b0 = wm * 16 + er, b1 = b0 + 8;
#pragma unroll
            for (int ni = 0; ni < 2; ni++) {
                int col = wn * 16 + ni * 8 + ec;
                gates_s[b0 * GATE_P + col]     += accA[ni][0] + accB[ni][0];
                gates_s[b0 * GATE_P + col + 1] += accA[ni][1] + accB[ni][1];
                gates_s[b1 * GATE_P + col]     += accA[ni][2] + accB[ni][2];
                gates_s[b1 * GATE_P + col + 1] += accA[ni][3] + accB[ni][3];
            }
        }
        __syncthreads();

        // cell update: 2 (b, hl) pairs per thread
        const int np = p ^ 1;
        for (int i = tid; i < 512; i += 256) {
            int b = i >> 4, hl = i & 15;
            float gi = gates_s[b * GATE_P + 0 * 16 + hl];
            float gf = gates_s[b * GATE_P + 1 * 16 + hl];
            float gg = gates_s[b * GATE_P + 2 * 16 + hl];
            float go = gates_s[b * GATE_P + 3 * 16 + hl];
            float iv = sigf(gi), fv = sigf(gf), gv = tanhf(gg), ov = sigf(go);
            float cc = c_s[i];
            float cn = fv * cc + iv * gv;
            float hn = ov * tanhf(cn);
            c_s[i] = cn;

            int col = x * 16 + hl;
            g_h16[np][d][b * Hsz + col] = __float2half(hn);

            if (layer == 0) {
                g_A16[d][(size_t)(t * 32 + b) * Hsz + col] = __float2half(hn);
            } else {
                outp[((size_t)b * Tsz + t) * (2 * Hsz) + (size_t)d * Hsz + col] = hn;
                if (extra) {
                    outp[(size_t)Bsz * Tsz * 2 * Hsz + (size_t)d * Bsz * Tsz * Hsz
                         + ((size_t)b * Tsz + t) * Hsz + col] = hn;
                }
            }
        }

        grid_barrier2(bid);
    }
}

extern "C" void kernel_launch(void* const* d_in, const int* in_sizes, int n_in,
                              void* d_out, int out_size) {
    const float* x     = (const float*)d_in[0];
    const float* Wih_f = (const float*)d_in[1];
    const float* Whh_f = (const float*)d_in[2];
    const float* b_f   = (const float*)d_in[3];
    const float* Wih_b = (const float*)d_in[4];
    const float* Whh_b = (const float*)d_in[5];
    const float* b_b   = (const float*)d_in[6];
    float* out = (float*)d_out;

    const long long full = (long long)Bsz * Tsz * 4 * Hsz;
    int extra = ((long long)out_size >= full) ? 1 : 0;

    static int attr_done = 0;
    if (!attr_done) {
        cudaFuncSetAttribute(tc_gemm_kernel,
                             cudaFuncAttributeMaxDynamicSharedMemorySize, SMEM_GEMM);
        cudaFuncSetAttribute(lstm_hmma_kernel,
                             cudaFuncAttributeMaxDynamicSharedMemorySize, SMEM_R);
        attr_done = 1;
    }

    dim3 gemmGrid(G4 / NT, MROWS / MT, 2);   // (32, 128, 2)
    dim3 stepGrid(64, 2);                    // 128 co-resident blocks

    conv_x_kernel<<<2048, 256>>>(x);
    for (int layer = 0; layer < 2; layer++) {
        conv_w_kernel<<<2048, 256>>>(Wih_f, Wih_b, layer);
        conv_rw_kernel<<<2048, 256>>>(Whh_f, Whh_b, layer);
        tc_gemm_kernel<<<gemmGrid, 256, SMEM_GEMM>>>(b_f, b_b, layer);
        lstm_hmma_kernel<<<stepGrid, 256, SMEM_R>>>(layer, out, extra);
    }
}

// round 9
// speedup vs baseline: 1.2745x; 1.0668x over previous
#include <cuda_runtime.h>
#include <cuda_fp16.h>
#include <math.h>
#include <stdint.h>

// BiRNN (2-layer bidirectional LSTM), B=32, T=512, H=1024.
// Round 9: recurrent kernel load pipeline restructured — B_lo/G issued
// pre-barrier, 3-slot rings with static wait_group schedule, 2-phase lead.
// fp16 math (A single fp16, W split hi+lo), GEMM unchanged from round 8.

#define Bsz 32
#define Tsz 512
#define Hsz 1024
#define G4  4096
#define MROWS (Tsz * Bsz) // 16384

// big input GEMM tiling
#define MT 128
#define NT 128
#define KT 32
#define KP 40                     // smem pitch in fp16 (80B)
#define BUFB (MT * KP * 2)        // 10240
#define STAGEB (3 * BUFB)         // A, Bh, Bl
#define SMEM_GEMM (2 * STAGEB)    // 61440

// recurrent tiling: K-tile 128 fp16 (256B) padded to 272B pitch
#define RPB 272
#define R_SA (32 * RPB)                 // 8704  (A tile)
#define R_TILEB (64 * RPB)              // 17408 (B tile)
#define R_RES (8 * R_TILEB)             // resident Whh_hi: 139264
#define OFF_A R_RES                     // 3-slot A ring
#define OFF_BLO (OFF_A + 3 * R_SA)      // 165376, 3-slot B_lo ring
#define OFF_GATES (OFF_BLO + 3 * R_TILEB) // 217600
#define GATE_P 68
#define OFF_C (OFF_GATES + 32 * GATE_P * 4) // 226304
#define SMEM_R (OFF_C + 2048)               // 228352

// ---------------- device globals -------------------------------------------
__device__ float g_G[2][(size_t)MROWS * G4];                 // x-part gates + bias
__device__ __align__(256) __half g_A16[2][(size_t)MROWS * Hsz];   // activations fp16
__device__ __align__(256) __half g_Wh16[2][(size_t)G4 * Hsz];     // Wih hi
__device__ __align__(256) __half g_Wl16[2][(size_t)G4 * Hsz];     // Wih lo
__device__ __align__(256) __half g_Rh16[2][(size_t)G4 * Hsz];     // Whh hi (reordered)
__device__ __align__(256) __half g_Rl16[2][(size_t)G4 * Hsz];     // Whh lo (reordered)
__device__ __align__(256) __half g_h16[2][2][Bsz * Hsz];          // [parity][dir]
__device__ unsigned g_cnt[4][64];
__device__ unsigned g_cnt2;
__device__ volatile unsigned g_gen;

// ---------------- helpers ---------------------------------------------------
__device__ __forceinline__ uint32_t smem_u32(const void* p) {
    uint32_t a;
    asm("{ .reg .u64 t; cvta.to.shared.u64 t, %1; cvt.u32.u64 %0, t; }" : "=r"(a) : "l"(p));
    return a;
}
__device__ __forceinline__ void cp16(uint32_t dst, const void* src) {
    asm volatile("cp.async.cg.shared.global [%0], [%1], 16;" :: "r"(dst), "l"(src));
}
#define CP_COMMIT() asm volatile("cp.async.commit_group;" ::: "memory")
#define CP_WAIT(n)  asm volatile("cp.async.wait_group %0;" :: "n"(n) : "memory")

__device__ __forceinline__ void ldm4(uint32_t* r, uint32_t a) {
    asm volatile("ldmatrix.sync.aligned.m8n8.x4.shared.b16 {%0,%1,%2,%3}, [%4];"
        : "=r"(r[0]), "=r"(r[1]), "=r"(r[2]), "=r"(r[3]) : "r"(a));
}
__device__ __forceinline__ void mma16816(float* d, const uint32_t* a, const uint32_t* b) {
    asm volatile(
        "mma.sync.aligned.m16n8k16.row.col.f32.f16.f16.f32 "
        "{%0,%1,%2,%3}, {%4,%5,%6,%7}, {%8,%9}, {%0,%1,%2,%3};"
        : "+f"(d[0]), "+f"(d[1]), "+f"(d[2]), "+f"(d[3])
        : "r"(a[0]), "r"(a[1]), "r"(a[2]), "r"(a[3]), "r"(b[0]), "r"(b[1]));
}

__device__ __forceinline__ void grid_barrier2(int bid) {
    __syncthreads();
    if (threadIdx.x == 0) {
        __threadfence();
        unsigned gen = g_gen;
        unsigned r = atomicAdd(&g_cnt[bid & 3][0], 1u);
        bool released = false;
        if (r == 31) {
            unsigned r2 = atomicAdd(&g_cnt2, 1u);
            if (r2 == 3) {
                g_cnt[0][0] = 0; g_cnt[1][0] = 0; g_cnt[2][0] = 0; g_cnt[3][0] = 0;
                g_cnt2 = 0;
                __threadfence();
                g_gen = gen + 1;
                released = true;
            }
        }
        if (!released) { while (g_gen == gen) { } }
        __threadfence();
    }
    __syncthreads();
}

__device__ __forceinline__ void split_f16(float v, __half& hi, __half& lo) {
    hi = __float2half(v);
    lo = __float2half(v - __half2float(hi));
}
__device__ __forceinline__ float sigf(float v) { return 1.0f / (1.0f + __expf(-v)); }

// ---------------- conversion kernels ---------------------------------------
__global__ void conv_x_kernel(const float* __restrict__ x) {
    const size_t N = (size_t)MROWS * Hsz;
    for (size_t i = blockIdx.x * blockDim.x + threadIdx.x; i < N; i += (size_t)gridDim.x * blockDim.x) {
        int r = (int)(i >> 10), h = (int)(i & 1023);
        int b = r & 31, t = r >> 5;
        g_A16[0][i] = __float2half(x[((size_t)b * Tsz + t) * Hsz + h]);
    }
}

__global__ void conv_w_kernel(const float* __restrict__ Wf, const float* __restrict__ Wb, int layer) {
    const size_t N = (size_t)G4 * Hsz;
    for (size_t i = blockIdx.x * blockDim.x + threadIdx.x; i < 2 * N; i += (size_t)gridDim.x * blockDim.x) {
        int d = i >= N;
        size_t j = d ? i - N : i;
        float v = (d ? Wb : Wf)[(size_t)layer * N + j];
        __half hi, lo; split_f16(v, hi, lo);
        g_Wh16[d][j] = hi; g_Wl16[d][j] = lo;
    }
}

// Whh: split + reorder rows: new row = x*64 + gate*16 + hl (orig gate*1024 + x*16 + hl)
__global__ void conv_rw_kernel(const float* __restrict__ Wf, const float* __restrict__ Wb, int layer) {
    const size_t N = (size_t)G4 * Hsz;
    for (size_t i = blockIdx.x * blockDim.x + threadIdx.x; i < 2 * N; i += (size_t)gridDim.x * blockDim.x) {
        int d = i >= N;
        size_t j = d ? i - N : i;
        int r = (int)(j >> 10), k = (int)(j & 1023);
        int g = r >> 10, h = r & 1023;
        int nr = (h >> 4) * 64 + g * 16 + (h & 15);
        float v = (d ? Wb : Wf)[(size_t)layer * N + j];
        __half hi, lo; split_f16(v, hi, lo);
        g_Rh16[d][(size_t)nr * Hsz + k] = hi;
        g_Rl16[d][(size_t)nr * Hsz + k] = lo;
    }
}

// ---------------- HMMA big input GEMM (fp16, 2 passes) ---------------------
__global__ void __launch_bounds__(256, 2) tc_gemm_kernel(
    const float* __restrict__ b_f, const float* __restrict__ b_b, int layer)
{
    extern __shared__ __align__(16) char sm[];
    const int d = blockIdx.z;
    const int mBlk = blockIdx.y * MT;
    const int nBlk = blockIdx.x * NT;
    const int tid = threadIdx.x, wid = tid >> 5, lid = tid & 31;

    const int aSel = (layer == 0) ? 0 : d;
    const __half* __restrict__ Aa = g_A16[aSel] + (size_t)mBlk * Hsz;
    const __half* __restrict__ Bh = g_Wh16[d] + (size_t)nBlk * Hsz;
    const __half* __restrict__ Bl = g_Wl16[d] + (size_t)nBlk * Hsz;
    const float* __restrict__ bias = (d == 0 ? b_f : b_b) + (size_t)layer * G4;

    const uint32_t smb = smem_u32(sm);

    const int lr0 = tid >> 2, lc0 = (tid & 3) * 8;
    const int lr1 = (tid + 256) >> 2;

    const int wm = wid & 1, wn = wid >> 1;
    const int ar = lid & 15, acg = lid >> 4;
    const int bnr = ((lid & 16) >> 1) | (lid & 7);
    const int bko = lid & 8;

    float acc[4][4][4] = {};

    {
        const uint32_t base = smb;
        uint32_t d0 = base + (uint32_t)(lr0 * KP + lc0) * 2;
        uint32_t d1 = base + (uint32_t)(lr1 * KP + lc0) * 2;
        size_t s0 = (size_t)lr0 * Hsz + lc0;
        size_t s1 = (size_t)lr1 * Hsz + lc0;
        cp16(d0 + 0 * BUFB, Aa + s0); cp16(d1 + 0 * BUFB, Aa + s1);
        cp16(d0 + 1 * BUFB, Bh + s0); cp16(d1 + 1 * BUFB, Bh + s1);
        cp16(d0 + 2 * BUFB, Bl + s0); cp16(d1 + 2 * BUFB, Bl + s1);
        CP_COMMIT();
    }

    const int NSTG = Hsz / KT; // 32
    for (int s = 0; s < NSTG; s++) {
        if (s + 1 < NSTG) {
            const int k0 = (s + 1) * KT;
            const uint32_t base = smb + ((s + 1) & 1) * STAGEB;
            uint32_t d0 = base + (uint32_t)(lr0 * KP + lc0) * 2;
            uint32_t d1 = base + (uint32_t)(lr1 * KP + lc0) * 2;
            size_t s0 = (size_t)lr0 * Hsz + k0 + lc0;
            size_t s1 = (size_t)lr1 * Hsz + k0 + lc0;
            cp16(d0 + 0 * BUFB, Aa + s0); cp16(d1 + 0 * BUFB, Aa + s1);
            cp16(d0 + 1 * BUFB, Bh + s0); cp16(d1 + 1 * BUFB, Bh + s1);
            cp16(d0 + 2 * BUFB, Bl + s0); cp16(d1 + 2 * BUFB, Bl + s1);
            CP_COMMIT();
            CP_WAIT(1);
        } else {
            CP_WAIT(0);
        }
        __syncthreads();

        const uint32_t base = smb + (s & 1) * STAGEB;
#pragma unroll
        for (int kc = 0; kc < 2; kc++) {
            uint32_t ah[4][4], bh[2][4], bl[2][4];
#pragma unroll
            for (int mi = 0; mi < 4; mi++) {
                uint32_t ao = base + (uint32_t)((wm * 64 + mi * 16 + ar) * KP + kc * 16 + acg * 8) * 2;
                ldm4(ah[mi], ao);
            }
#pragma unroll
            for (int g = 0; g < 2; g++) {
                uint32_t bo = (uint32_t)((wn * 32 + g * 16 + bnr) * KP + kc * 16 + bko) * 2;
                ldm4(bh[g], base + BUFB + bo);
                ldm4(bl[g], base + 2 * BUFB + bo);
            }
#pragma unroll
            for (int mi = 0; mi < 4; mi++)
#pragma unroll
                for (int ni = 0; ni < 4; ni++)
                    mma16816(acc[mi][ni], ah[mi], &bh[ni >> 1][(ni & 1) * 2]);
#pragma unroll
            for (int mi = 0; mi < 4; mi++)
#pragma unroll
                for (int ni = 0; ni < 4; ni++)
                    mma16816(acc[mi][ni], ah[mi], &bl[ni >> 1][(ni & 1) * 2]);
        }
        __syncthreads();
    }

    const int er = lid >> 2, ec = (lid & 3) * 2;
#pragma unroll
    for (int mi = 0; mi < 4; mi++) {
#pragma unroll
        for (int ni = 0; ni < 4; ni++) {
            int gm = mBlk + wm * 64 + mi * 16 + er;
            int gn = nBlk + wn * 32 + ni * 8 + ec;
            float bv0 = bias[gn], bv1 = bias[gn + 1];
            float* p0 = g_G[d] + (size_t)gm * G4 + gn;
            p0[0] = acc[mi][ni][0] + bv0;
            p0[1] = acc[mi][ni][1] + bv1;
            float* p1 = p0 + (size_t)8 * G4;
            p1[0] = acc[mi][ni][2] + bv0;
            p1[1] = acc[mi][ni][3] + bv1;
        }
    }
}

// ---------------- persistent HMMA recurrent LSTM (fp16) --------------------
// Grid (64, 2), 256 threads, 8 warps 2x4 (warp tile 16x16). Whh_hi resident.
// B_lo + G issued PRE-barrier; A post-barrier; 3-slot rings, phase k issues
// tiles k+2; static wait_group schedule (1 / 2 / 0).
__global__ void __launch_bounds__(256) lstm_hmma_kernel(
    int layer, float* __restrict__ outp, int extra)
{
    extern __shared__ __align__(16) char rsm[];
    const int x = blockIdx.x, d = blockIdx.y;
    const int bid = blockIdx.x + blockIdx.y * 64;
    const int tid = threadIdx.x, wid = tid >> 5, lid = tid & 31;
    const int wm = wid & 1, wn = wid >> 1;

    const uint32_t smb = smem_u32(rsm);
    float* gates_s = (float*)(rsm + OFF_GATES);
    float* c_s = (float*)(rsm + OFF_C);

    const __half* __restrict__ Bh = g_Rh16[d] + (size_t)(x * 64) * Hsz;
    const __half* __restrict__ Bl = g_Rl16[d] + (size_t)(x * 64) * Hsz;

    // load maps
    const int arow = tid >> 3, ac2 = (tid & 7) * 2;   // A: 32 rows x 16 chunks
    const int brow = tid >> 2, bc4 = (tid & 3) * 4;   // B: 64 rows x 16 chunks

    // Resident Whh_hi: 8 tiles of 64x128.
#pragma unroll
    for (int kt = 0; kt < 8; kt++) {
        uint32_t dst = smb + kt * R_TILEB + (uint32_t)(brow * RPB + bc4 * 16);
        const __half* src = Bh + (size_t)brow * Hsz + kt * 128 + bc4 * 8;
#pragma unroll
        for (int j = 0; j < 4; j++) cp16(dst + j * 16, src + j * 8);
    }
    CP_COMMIT();

    for (int i = tid; i < 512; i += 256) {
        int b = i >> 4, col = x * 16 + (i & 15);
        g_h16[0][d][b * Hsz + col] = __float2half(0.f);
        g_h16[1][d][b * Hsz + col] = __float2half(0.f);
        c_s[i] = 0.f;
    }
    CP_WAIT(0);
    grid_barrier2(bid);

    // fragment maps
    const int ar = lid & 15, acg = lid >> 4;
    const int bnr = ((lid & 16) >> 1) | (lid & 7);
    const int bk8 = (lid & 8) >> 3;
    const uint32_t aRowOff = (uint32_t)((wm * 16 + ar) * RPB);
    const uint32_t bRowOff = (uint32_t)((wn * 16 + bnr) * RPB);

    // G prefetch map
    const int gb = tid >> 3, gseg = tid & 7;
    const uint32_t gdst = smb + OFF_GATES + (uint32_t)(gb * GATE_P + gseg * 8) * 4;
    const size_t goff0 = (size_t)(gseg >> 1) * 1024 + x * 16 + (gseg & 1) * 8;

    const uint32_t aOffT = (uint32_t)(arow * RPB + ac2 * 16);
    const uint32_t bOffT = (uint32_t)(brow * RPB + bc4 * 16);

    // pre-issue for step 0: Blo0, Blo1, G
#pragma unroll
    for (int kt = 0; kt < 2; kt++) {
        uint32_t dst = smb + OFF_BLO + kt * R_TILEB + bOffT;
        const __half* src = Bl + (size_t)brow * Hsz + kt * 128 + bc4 * 8;
#pragma unroll
        for (int j = 0; j < 4; j++) cp16(dst + j * 16, src + j * 8);
        CP_COMMIT();
    }
    {
        const int t0 = (d == 0) ? 0 : (Tsz - 1);
        cp16(gdst, g_G[d] + (size_t)(t0 * 32 + gb) * G4 + goff0);
        cp16(gdst + 16, g_G[d] + (size_t)(t0 * 32 + gb) * G4 + goff0 + 4);
        CP_COMMIT();
    }

    for (int s = 0; s < Tsz; s++) {
        const int p = s & 1;
        const int t = (d == 0) ? s : (Tsz - 1 - s);
        const __half* __restrict__ Ah = g_h16[p][d];

        // A tiles 0, 1 (h is valid after the barrier)
#pragma unroll
        for (int kt = 0; kt < 2; kt++) {
            uint32_t dst = smb + OFF_A + kt * R_SA + aOffT;
            const __half* src = Ah + (size_t)arow * Hsz + kt * 128 + ac2 * 8;
            cp16(dst, src);
            cp16(dst + 16, src + 8);
            CP_COMMIT();
        }

        float accA[2][4] = {};   // A x B_hi
        float accB[2][4] = {};   // A x B_lo

#pragma unroll
        for (int kt = 0; kt < 8; kt++) {
            if (kt == 0)      { CP_WAIT(1); }
            else if (kt == 7) { CP_WAIT(0); }
            else              { CP_WAIT(2); }
            __syncthreads();

            if (kt < 6) {
                const int kn = kt + 2;
                uint32_t bdst = smb + OFF_BLO + (kn % 3) * R_TILEB + bOffT;
                const __half* bsrc = Bl + (size_t)brow * Hsz + kn * 128 + bc4 * 8;
#pragma unroll
                for (int j = 0; j < 4; j++) cp16(bdst + j * 16, bsrc + j * 8);
                CP_COMMIT();
                uint32_t adst = smb + OFF_A + (kn % 3) * R_SA + aOffT;
                const __half* asrc = Ah + (size_t)arow * Hsz + kn * 128 + ac2 * 8;
                cp16(adst, asrc);
                cp16(adst + 16, asrc + 8);
                CP_COMMIT();
            }

            const uint32_t stgA = smb + OFF_A + (kt % 3) * R_SA;
            const uint32_t stgB = smb + OFF_BLO + (kt % 3) * R_TILEB;
            const uint32_t bres = smb + kt * R_TILEB;
#pragma unroll
            for (int kc = 0; kc < 8; kc++) {
                uint32_t ah[4], bh[4], bl[4];
                ldm4(ah, stgA + aRowOff + (uint32_t)((kc * 2 + acg) * 16));
                uint32_t bco = (uint32_t)((kc * 2 + bk8) * 16);
                ldm4(bh, bres + bRowOff + bco);
                ldm4(bl, stgB + bRowOff + bco);
                mma16816(accA[0], ah, &bh[0]);
                mma16816(accA[1], ah, &bh[2]);
                mma16816(accB[0], ah, &bl[0]);
                mma16816(accB[1], ah, &bl[2]);
            }
        }
        __syncthreads();

        // epilogue: gates_s (holds prefetched G) += acc
        {
            const int er = lid >> 2, ec = (lid & 3) * 2;
            const int b0 = wm * 16 + er, b1 = b0 + 8;
#pragma unroll
            for (int ni = 0; ni < 2; ni++) {
                int col = wn * 16 + ni * 8 + ec;
                gates_s[b0 * GATE_P + col]     += accA[ni][0] + accB[ni][0];
                gates_s[b0 * GATE_P + col + 1] += accA[ni][1] + accB[ni][1];
                gates_s[b1 * GATE_P + col]     += accA[ni][2] + accB[ni][2];
                gates_s[b1 * GATE_P + col + 1] += accA[ni][3] + accB[ni][3];
            }
        }
        __syncthreads();

        // cell update: 2 (b, hl) pairs per thread
        const int np = p ^ 1;
        for (int i = tid; i < 512; i += 256) {
            int b = i >> 4, hl = i & 15;
            float gi = gates_s[b * GATE_P + 0 * 16 + hl];
            float gf = gates_s[b * GATE_P + 1 * 16 + hl];
            float gg = gates_s[b * GATE_P + 2 * 16 + hl];
            float go = gates_s[b * GATE_P + 3 * 16 + hl];
            float iv = sigf(gi), fv = sigf(gf), gv = tanhf(gg), ov = sigf(go);
            float cc = c_s[i];
            float cn = fv * cc + iv * gv;
            float hn = ov * tanhf(cn);
            c_s[i] = cn;

            int col = x * 16 + hl;
            g_h16[np][d][b * Hsz + col] = __float2half(hn);

            if (layer == 0) {
                g_A16[d][(size_t)(t * 32 + b) * Hsz + col] = __float2half(hn);
            } else {
                outp[((size_t)b * Tsz + t) * (2 * Hsz) + (size_t)d * Hsz + col] = hn;
                if (extra) {
                    outp[(size_t)Bsz * Tsz * 2 * Hsz + (size_t)d * Bsz * Tsz * Hsz
                         + ((size_t)b * Tsz + t) * Hsz + col] = hn;
                }
            }
        }
        __syncthreads();   // gates_s reads done before next step's G overwrite

        // pre-issue for step s+1: Blo0, Blo1, G (independent of h)
        if (s + 1 < Tsz) {
#pragma unroll
            for (int kt = 0; kt < 2; kt++) {
                uint32_t dst = smb + OFF_BLO + kt * R_TILEB + bOffT;
                const __half* src = Bl + (size_t)brow * Hsz + kt * 128 + bc4 * 8;
#pragma unroll
                for (int j = 0; j < 4; j++) cp16(dst + j * 16, src + j * 8);
                CP_COMMIT();
            }
            const int tn = (d == 0) ? (s + 1) : (Tsz - 2 - s);
            cp16(gdst, g_G[d] + (size_t)(tn * 32 + gb) * G4 + goff0);
            cp16(gdst + 16, g_G[d] + (size_t)(tn * 32 + gb) * G4 + goff0 + 4);
            CP_COMMIT();
        }

        grid_barrier2(bid);
    }
}

extern "C" void kernel_launch(void* const* d_in, const int* in_sizes, int n_in,
                              void* d_out, int out_size) {
    const float* x     = (const float*)d_in[0];
    const float* Wih_f = (const float*)d_in[1];
    const float* Whh_f = (const float*)d_in[2];
    const float* b_f   = (const float*)d_in[3];
    const float* Wih_b = (const float*)d_in[4];
    const float* Whh_b = (const float*)d_in[5];
    const float* b_b   = (const float*)d_in[6];
    float* out = (float*)d_out;

    const long long full = (long long)Bsz * Tsz * 4 * Hsz;
    int extra = ((long long)out_size >= full) ? 1 : 0;

    static int attr_done = 0;
    if (!attr_done) {
        cudaFuncSetAttribute(tc_gemm_kernel,
                             cudaFuncAttributeMaxDynamicSharedMemorySize, SMEM_GEMM);
        cudaFuncSetAttribute(lstm_hmma_kernel,
                             cudaFuncAttributeMaxDynamicSharedMemorySize, SMEM_R);
        attr_done = 1;
    }

    dim3 gemmGrid(G4 / NT, MROWS / MT, 2);   // (32, 128, 2)
    dim3 stepGrid(64, 2);                    // 128 co-resident blocks

    conv_x_kernel<<<2048, 256>>>(x);
    for (int layer = 0; layer < 2; layer++) {
        conv_w_kernel<<<2048, 256>>>(Wih_f, Wih_b, layer);
        conv_rw_kernel<<<2048, 256>>>(Whh_f, Whh_b, layer);
        tc_gemm_kernel<<<gemmGrid, 256, SMEM_GEMM>>>(b_f, b_b, layer);
        lstm_hmma_kernel<<<stepGrid, 256, SMEM_R>>>(layer, out, extra);
    }
}

// round 10
// speedup vs baseline: 1.6944x; 1.3294x over previous
#include <cuda_runtime.h>
#include <cuda_fp16.h>
#include <math.h>
#include <stdint.h>

// BiRNN (2-layer bidirectional LSTM), B=32, T=512, H=1024.
// Round 10: recurrent kernel drops the W_lo pass (Whh single fp16) —
// Whh_hi + full A resident per step, no waits/syncs inside the phase loop.
// Input GEMM keeps the W hi+lo split (G stays accurate).

#define Bsz 32
#define Tsz 512
#define Hsz 1024
#define G4  4096
#define MROWS (Tsz * Bsz) // 16384

// big input GEMM tiling
#define MT 128
#define NT 128
#define KT 32
#define KP 40                     // smem pitch in fp16 (80B)
#define BUFB (MT * KP * 2)        // 10240
#define STAGEB (3 * BUFB)         // A, Bh, Bl
#define SMEM_GEMM (2 * STAGEB)    // 61440

// recurrent tiling: K-tile 128 fp16 (256B) padded to 272B pitch
#define RPB 272
#define R_SA (32 * RPB)                 // 8704  (one A tile)
#define R_TILEB (64 * RPB)              // 17408 (one B tile)
#define R_RES (8 * R_TILEB)             // resident Whh_hi: 139264
#define OFF_A R_RES                     // full A: 8 tiles
#define OFF_GATES (OFF_A + 8 * R_SA)    // 208896
#define GATE_P 68
#define OFF_C (OFF_GATES + 32 * GATE_P * 4) // 217600
#define SMEM_R (OFF_C + 2048)               // 219648

// ---------------- device globals -------------------------------------------
__device__ float g_G[2][(size_t)MROWS * G4];                 // x-part gates + bias
__device__ __align__(256) __half g_A16[2][(size_t)MROWS * Hsz];   // activations fp16
__device__ __align__(256) __half g_Wh16[2][(size_t)G4 * Hsz];     // Wih hi
__device__ __align__(256) __half g_Wl16[2][(size_t)G4 * Hsz];     // Wih lo
__device__ __align__(256) __half g_Rh16[2][(size_t)G4 * Hsz];     // Whh fp16 (reordered)
__device__ __align__(256) __half g_h16[2][2][Bsz * Hsz];          // [parity][dir]
__device__ unsigned g_cnt[4][64];
__device__ unsigned g_cnt2;
__device__ volatile unsigned g_gen;

// ---------------- helpers ---------------------------------------------------
__device__ __forceinline__ uint32_t smem_u32(const void* p) {
    uint32_t a;
    asm("{ .reg .u64 t; cvta.to.shared.u64 t, %1; cvt.u32.u64 %0, t; }" : "=r"(a) : "l"(p));
    return a;
}
__device__ __forceinline__ void cp16(uint32_t dst, const void* src) {
    asm volatile("cp.async.cg.shared.global [%0], [%1], 16;" :: "r"(dst), "l"(src));
}
#define CP_COMMIT() asm volatile("cp.async.commit_group;" ::: "memory")
#define CP_WAIT(n)  asm volatile("cp.async.wait_group %0;" :: "n"(n) : "memory")

__device__ __forceinline__ void ldm4(uint32_t* r, uint32_t a) {
    asm volatile("ldmatrix.sync.aligned.m8n8.x4.shared.b16 {%0,%1,%2,%3}, [%4];"
        : "=r"(r[0]), "=r"(r[1]), "=r"(r[2]), "=r"(r[3]) : "r"(a));
}
__device__ __forceinline__ void mma16816(float* d, const uint32_t* a, const uint32_t* b) {
    asm volatile(
        "mma.sync.aligned.m16n8k16.row.col.f32.f16.f16.f32 "
        "{%0,%1,%2,%3}, {%4,%5,%6,%7}, {%8,%9}, {%0,%1,%2,%3};"
        : "+f"(d[0]), "+f"(d[1]), "+f"(d[2]), "+f"(d[3])
        : "r"(a[0]), "r"(a[1]), "r"(a[2]), "r"(a[3]), "r"(b[0]), "r"(b[1]));
}

__device__ __forceinline__ void grid_barrier2(int bid) {
    __syncthreads();
    if (threadIdx.x == 0) {
        __threadfence();
        unsigned gen = g_gen;
        unsigned r = atomicAdd(&g_cnt[bid & 3][0], 1u);
        bool released = false;
        if (r == 31) {
            unsigned r2 = atomicAdd(&g_cnt2, 1u);
            if (r2 == 3) {
                g_cnt[0][0] = 0; g_cnt[1][0] = 0; g_cnt[2][0] = 0; g_cnt[3][0] = 0;
                g_cnt2 = 0;
                __threadfence();
                g_gen = gen + 1;
                released = true;
            }
        }
        if (!released) { while (g_gen == gen) { } }
        __threadfence();
    }
    __syncthreads();
}

__device__ __forceinline__ void split_f16(float v, __half& hi, __half& lo) {
    hi = __float2half(v);
    lo = __float2half(v - __half2float(hi));
}
__device__ __forceinline__ float sigf(float v) { return 1.0f / (1.0f + __expf(-v)); }

// ---------------- conversion kernels ---------------------------------------
__global__ void conv_x_kernel(const float* __restrict__ x) {
    const size_t N = (size_t)MROWS * Hsz;
    for (size_t i = blockIdx.x * blockDim.x + threadIdx.x; i < N; i += (size_t)gridDim.x * blockDim.x) {
        int r = (int)(i >> 10), h = (int)(i & 1023);
        int b = r & 31, t = r >> 5;
        g_A16[0][i] = __float2half(x[((size_t)b * Tsz + t) * Hsz + h]);
    }
}

__global__ void conv_w_kernel(const float* __restrict__ Wf, const float* __restrict__ Wb, int layer) {
    const size_t N = (size_t)G4 * Hsz;
    for (size_t i = blockIdx.x * blockDim.x + threadIdx.x; i < 2 * N; i += (size_t)gridDim.x * blockDim.x) {
        int d = i >= N;
        size_t j = d ? i - N : i;
        float v = (d ? Wb : Wf)[(size_t)layer * N + j];
        __half hi, lo; split_f16(v, hi, lo);
        g_Wh16[d][j] = hi; g_Wl16[d][j] = lo;
    }
}

// Whh: fp16 + reorder rows: new row = x*64 + gate*16 + hl (orig gate*1024 + x*16 + hl)
__global__ void conv_rw_kernel(const float* __restrict__ Wf, const float* __restrict__ Wb, int layer) {
    const size_t N = (size_t)G4 * Hsz;
    for (size_t i = blockIdx.x * blockDim.x + threadIdx.x; i < 2 * N; i += (size_t)gridDim.x * blockDim.x) {
        int d = i >= N;
        size_t j = d ? i - N : i;
        int r = (int)(j >> 10), k = (int)(j & 1023);
        int g = r >> 10, h = r & 1023;
        int nr = (h >> 4) * 64 + g * 16 + (h & 15);
        g_Rh16[d][(size_t)nr * Hsz + k] = __float2half((d ? Wb : Wf)[(size_t)layer * N + j]);
    }
}

// ---------------- HMMA big input GEMM (fp16, 2 passes) ---------------------
__global__ void __launch_bounds__(256, 2) tc_gemm_kernel(
    const float* __restrict__ b_f, const float* __restrict__ b_b, int layer)
{
    extern __shared__ __align__(16) char sm[];
    const int d = blockIdx.z;
    const int mBlk = blockIdx.y * MT;
    const int nBlk = blockIdx.x * NT;
    const int tid = threadIdx.x, wid = tid >> 5, lid = tid & 31;

    const int aSel = (layer == 0) ? 0 : d;
    const __half* __restrict__ Aa = g_A16[aSel] + (size_t)mBlk * Hsz;
    const __half* __restrict__ Bh = g_Wh16[d] + (size_t)nBlk * Hsz;
    const __half* __restrict__ Bl = g_Wl16[d] + (size_t)nBlk * Hsz;
    const float* __restrict__ bias = (d == 0 ? b_f : b_b) + (size_t)layer * G4;

    const uint32_t smb = smem_u32(sm);

    const int lr0 = tid >> 2, lc0 = (tid & 3) * 8;
    const int lr1 = (tid + 256) >> 2;

    const int wm = wid & 1, wn = wid >> 1;
    const int ar = lid & 15, acg = lid >> 4;
    const int bnr = ((lid & 16) >> 1) | (lid & 7);
    const int bko = lid & 8;

    float acc[4][4][4] = {};

    {
        const uint32_t base = smb;
        uint32_t d0 = base + (uint32_t)(lr0 * KP + lc0) * 2;
        uint32_t d1 = base + (uint32_t)(lr1 * KP + lc0) * 2;
        size_t s0 = (size_t)lr0 * Hsz + lc0;
        size_t s1 = (size_t)lr1 * Hsz + lc0;
        cp16(d0 + 0 * BUFB, Aa + s0); cp16(d1 + 0 * BUFB, Aa + s1);
        cp16(d0 + 1 * BUFB, Bh + s0); cp16(d1 + 1 * BUFB, Bh + s1);
        cp16(d0 + 2 * BUFB, Bl + s0); cp16(d1 + 2 * BUFB, Bl + s1);
        CP_COMMIT();
    }

    const int NSTG = Hsz / KT; // 32
    for (int s = 0; s < NSTG; s++) {
        if (s + 1 < NSTG) {
            const int k0 = (s + 1) * KT;
            const uint32_t base = smb + ((s + 1) & 1) * STAGEB;
            uint32_t d0 = base + (uint32_t)(lr0 * KP + lc0) * 2;
            uint32_t d1 = base + (uint32_t)(lr1 * KP + lc0) * 2;
            size_t s0 = (size_t)lr0 * Hsz + k0 + lc0;
            size_t s1 = (size_t)lr1 * Hsz + k0 + lc0;
            cp16(d0 + 0 * BUFB, Aa + s0); cp16(d1 + 0 * BUFB, Aa + s1);
            cp16(d0 + 1 * BUFB, Bh + s0); cp16(d1 + 1 * BUFB, Bh + s1);
            cp16(d0 + 2 * BUFB, Bl + s0); cp16(d1 + 2 * BUFB, Bl + s1);
            CP_COMMIT();
            CP_WAIT(1);
        } else {
            CP_WAIT(0);
        }
        __syncthreads();

        const uint32_t base = smb + (s & 1) * STAGEB;
#pragma unroll
        for (int kc = 0; kc < 2; kc++) {
            uint32_t ah[4][4], bh[2][4], bl[2][4];
#pragma unroll
            for (int mi = 0; mi < 4; mi++) {
                uint32_t ao = base + (uint32_t)((wm * 64 + mi * 16 + ar) * KP + kc * 16 + acg * 8) * 2;
                ldm4(ah[mi], ao);
            }
#pragma unroll
            for (int g = 0; g < 2; g++) {
                uint32_t bo = (uint32_t)((wn * 32 + g * 16 + bnr) * KP + kc * 16 + bko) * 2;
                ldm4(bh[g], base + BUFB + bo);
                ldm4(bl[g], base + 2 * BUFB + bo);
            }
#pragma unroll
            for (int mi = 0; mi < 4; mi++)
#pragma unroll
                for (int ni = 0; ni < 4; ni++)
                    mma16816(acc[mi][ni], ah[mi], &bh[ni >> 1][(ni & 1) * 2]);
#pragma unroll
            for (int mi = 0; mi < 4; mi++)
#pragma unroll
                for (int ni = 0; ni < 4; ni++)
                    mma16816(acc[mi][ni], ah[mi], &bl[ni >> 1][(ni & 1) * 2]);
        }
        __syncthreads();
    }

    const int er = lid >> 2, ec = (lid & 3) * 2;
#pragma unroll
    for (int mi = 0; mi < 4; mi++) {
#pragma unroll
        for (int ni = 0; ni < 4; ni++) {
            int gm = mBlk + wm * 64 + mi * 16 + er;
            int gn = nBlk + wn * 32 + ni * 8 + ec;
            float bv0 = bias[gn], bv1 = bias[gn + 1];
            float* p0 = g_G[d] + (size_t)gm * G4 + gn;
            p0[0] = acc[mi][ni][0] + bv0;
            p0[1] = acc[mi][ni][1] + bv1;
            float* p1 = p0 + (size_t)8 * G4;
            p1[0] = acc[mi][ni][2] + bv0;
            p1[1] = acc[mi][ni][3] + bv1;
        }
    }
}

// ---------------- persistent HMMA recurrent LSTM (fp16, single W pass) -----
// Grid (64, 2), 256 threads, 8 warps 2x4 (warp tile 16x16).
// Whh resident in smem; full A loaded once per step; G prefetched pre-barrier.
// No waits/syncs inside the 8-phase compute loop.
__global__ void __launch_bounds__(256) lstm_hmma_kernel(
    int layer, float* __restrict__ outp, int extra)
{
    extern __shared__ __align__(16) char rsm[];
    const int x = blockIdx.x, d = blockIdx.y;
    const int bid = blockIdx.x + blockIdx.y * 64;
    const int tid = threadIdx.x, wid = tid >> 5, lid = tid & 31;
    const int wm = wid & 1, wn = wid >> 1;

    const uint32_t smb = smem_u32(rsm);
    float* gates_s = (float*)(rsm + OFF_GATES);
    float* c_s = (float*)(rsm + OFF_C);

    const __half* __restrict__ Bh = g_Rh16[d] + (size_t)(x * 64) * Hsz;

    // load maps
    const int arow = tid >> 3, ac2 = (tid & 7) * 2;   // A: 32 rows x 16 chunks
    const int brow = tid >> 2, bc4 = (tid & 3) * 4;   // B: 64 rows x 16 chunks

    // Resident Whh: 8 tiles of 64x128.
#pragma unroll
    for (int kt = 0; kt < 8; kt++) {
        uint32_t dst = smb + kt * R_TILEB + (uint32_t)(brow * RPB + bc4 * 16);
        const __half* src = Bh + (size_t)brow * Hsz + kt * 128 + bc4 * 8;
#pragma unroll
        for (int j = 0; j < 4; j++) cp16(dst + j * 16, src + j * 8);
    }
    CP_COMMIT();

    for (int i = tid; i < 512; i += 256) {
        int b = i >> 4, col = x * 16 + (i & 15);
        g_h16[0][d][b * Hsz + col] = __float2half(0.f);
        g_h16[1][d][b * Hsz + col] = __float2half(0.f);
        c_s[i] = 0.f;
    }
    CP_WAIT(0);
    grid_barrier2(bid);

    // fragment maps
    const int ar = lid & 15, acg = lid >> 4;
    const int bnr = ((lid & 16) >> 1) | (lid & 7);
    const int bk8 = (lid & 8) >> 3;
    const uint32_t aRowOff = (uint32_t)((wm * 16 + ar) * RPB);
    const uint32_t bRowOff = (uint32_t)((wn * 16 + bnr) * RPB);

    // G prefetch map
    const int gb = tid >> 3, gseg = tid & 7;
    const uint32_t gdst = smb + OFF_GATES + (uint32_t)(gb * GATE_P + gseg * 8) * 4;
    const size_t goff0 = (size_t)(gseg >> 1) * 1024 + x * 16 + (gseg & 1) * 8;

    const uint32_t aOffT = (uint32_t)(arow * RPB + ac2 * 16);

    // pre-issue G for step 0
    {
        const int t0 = (d == 0) ? 0 : (Tsz - 1);
        cp16(gdst, g_G[d] + (size_t)(t0 * 32 + gb) * G4 + goff0);
        cp16(gdst + 16, g_G[d] + (size_t)(t0 * 32 + gb) * G4 + goff0 + 4);
        CP_COMMIT();
    }

    for (int s = 0; s < Tsz; s++) {
        const int p = s & 1;
        const int t = (d == 0) ? s : (Tsz - 1 - s);
        const __half* __restrict__ Ah = g_h16[p][d];

        // load full A (8 tiles, 64KB) in one group
#pragma unroll
        for (int kt = 0; kt < 8; kt++) {
            uint32_t dst = smb + OFF_A + kt * R_SA + aOffT;
            const __half* src = Ah + (size_t)arow * Hsz + kt * 128 + ac2 * 8;
            cp16(dst, src);
            cp16(dst + 16, src + 8);
        }
        CP_COMMIT();
        CP_WAIT(0);   // A + G resident
        __syncthreads();

        float accA[2][4] = {};

        // 8 phases, no waits, no syncs
#pragma unroll
        for (int kt = 0; kt < 8; kt++) {
            const uint32_t stgA = smb + OFF_A + kt * R_SA;
            const uint32_t bres = smb + kt * R_TILEB;
#pragma unroll
            for (int kc = 0; kc < 8; kc++) {
                uint32_t ah[4], bh[4];
                ldm4(ah, stgA + aRowOff + (uint32_t)((kc * 2 + acg) * 16));
                ldm4(bh, bres + bRowOff + (uint32_t)((kc * 2 + bk8) * 16));
                mma16816(accA[0], ah, &bh[0]);
                mma16816(accA[1], ah, &bh[2]);
            }
        }

        // epilogue: gates_s (holds prefetched G) += acc (disjoint per warp)
        {
            const int er = lid >> 2, ec = (lid & 3) * 2;
            const int b0 = wm * 16 + er, b1 = b0 + 8;
#pragma unroll
            for (int ni = 0; ni < 2; ni++) {
                int col = wn * 16 + ni * 8 + ec;
                gates_s[b0 * GATE_P + col]     += accA[ni][0];
                gates_s[b0 * GATE_P + col + 1] += accA[ni][1];
                gates_s[b1 * GATE_P + col]     += accA[ni][2];
                gates_s[b1 * GATE_P + col + 1] += accA[ni][3];
            }
        }
        __syncthreads();

        // cell update: 2 (b, hl) pairs per thread
        const int np = p ^ 1;
        for (int i = tid; i < 512; i += 256) {
            int b = i >> 4, hl = i & 15;
            float gi = gates_s[b * GATE_P + 0 * 16 + hl];
            float gf = gates_s[b * GATE_P + 1 * 16 + hl];
            float gg = gates_s[b * GATE_P + 2 * 16 + hl];
            float go = gates_s[b * GATE_P + 3 * 16 + hl];
            float iv = sigf(gi), fv = sigf(gf), gv = tanhf(gg), ov = sigf(go);
            float cc = c_s[i];
            float cn = fv * cc + iv * gv;
            float hn = ov * tanhf(cn);
            c_s[i] = cn;

            int col = x * 16 + hl;
            g_h16[np][d][b * Hsz + col] = __float2half(hn);

            if (layer == 0) {
                g_A16[d][(size_t)(t * 32 + b) * Hsz + col] = __float2half(hn);
            } else {
                outp[((size_t)b * Tsz + t) * (2 * Hsz) + (size_t)d * Hsz + col] = hn;
                if (extra) {
                    outp[(size_t)Bsz * Tsz * 2 * Hsz + (size_t)d * Bsz * Tsz * Hsz
                         + ((size_t)b * Tsz + t) * Hsz + col] = hn;
                }
            }
        }
        __syncthreads();   // gates_s reads done before next step's G overwrite

        // pre-issue G for step s+1 (independent of h)
        if (s + 1 < Tsz) {
            const int tn = (d == 0) ? (s + 1) : (Tsz - 2 - s);
            cp16(gdst, g_G[d] + (size_t)(tn * 32 + gb) * G4 + goff0);
            cp16(gdst + 16, g_G[d] + (size_t)(tn * 32 + gb) * G4 + goff0 + 4);
            CP_COMMIT();
        }

        grid_barrier2(bid);
    }
}

extern "C" void kernel_launch(void* const* d_in, const int* in_sizes, int n_in,
                              void* d_out, int out_size) {
    const float* x     = (const float*)d_in[0];
    const float* Wih_f = (const float*)d_in[1];
    const float* Whh_f = (const float*)d_in[2];
    const float* b_f   = (const float*)d_in[3];
    const float* Wih_b = (const float*)d_in[4];
    const float* Whh_b = (const float*)d_in[5];
    const float* b_b   = (const float*)d_in[6];
    float* out = (float*)d_out;

    const long long full = (long long)Bsz * Tsz * 4 * Hsz;
    int extra = ((long long)out_size >= full) ? 1 : 0;

    static int attr_done = 0;
    if (!attr_done) {
        cudaFuncSetAttribute(tc_gemm_kernel,
                             cudaFuncAttributeMaxDynamicSharedMemorySize, SMEM_GEMM);
        cudaFuncSetAttribute(lstm_hmma_kernel,
                             cudaFuncAttributeMaxDynamicSharedMemorySize, SMEM_R);
        attr_done = 1;
    }

    dim3 gemmGrid(G4 / NT, MROWS / MT, 2);   // (32, 128, 2)
    dim3 stepGrid(64, 2);                    // 128 co-resident blocks

    conv_x_kernel<<<2048, 256>>>(x);
    for (int layer = 0; layer < 2; layer++) {
        conv_w_kernel<<<2048, 256>>>(Wih_f, Wih_b, layer);
        conv_rw_kernel<<<2048, 256>>>(Whh_f, Whh_b, layer);
        tc_gemm_kernel<<<gemmGrid, 256, SMEM_GEMM>>>(b_f, b_b, layer);
        lstm_hmma_kernel<<<stepGrid, 256, SMEM_R>>>(layer, out, extra);
    }
}